// round 6
// baseline (speedup 1.0000x reference)
#include <cuda_runtime.h>

// DenseRadiusGraph: B=16 graphs, N=2048 nodes, D=3, cutoff=10, K=32.
// Output (float32, concat, M = B*N*K = 1048576):
//   [0,M) row ids, [M,2M) col ids, [2M,3M) weights, [3M,4M) valid flags.
//
// R6: LDS-broadcast position tile (lat 29 / floor 2 vs LDG 39/4) at single-
// wave occupancy (512 blocks x 512 thr, 52.3KB smem, 4 blocks/SM), inner
// loop processes j-PAIRS with packed fma.rn.f32x2 (FFMA2). Exact reference
// math re-derived per element in the rare pass-path -> selection unchanged.

#define BGRAPHS 16
#define NNODES  2048
#define NPAIRS  (NNODES / 2)
#define KNBR    32
#define TPB     512
#define NODESB  64                    // nodes per block
#define QUART   8                     // sub-threads per node
#define SPANP   (NPAIRS / QUART)      // 128 j-pairs per sub-thread
#define CAPS    40
#define CHUNKS  (NNODES / NODESB)     // 32 -> grid = 512 blocks

#define SMEM_BYTES (NNODES * 16 + NODESB * CAPS * 8 + NODESB * 4)

extern __shared__ unsigned char smem_raw[];

__device__ __forceinline__ unsigned long long fma_f32x2(
    unsigned long long a, unsigned long long b, unsigned long long c)
{
    unsigned long long d;
    asm("fma.rn.f32x2 %0, %1, %2, %3;" : "=l"(d) : "l"(a), "l"(b), "l"(c));
    return d;
}

__device__ __forceinline__ unsigned long long bcast_f32x2(float v)
{
    unsigned long long d;
    unsigned int u = __float_as_uint(v);
    asm("mov.b64 %0, {%1, %1};" : "=l"(d) : "r"(u));
    return d;
}

__global__ __launch_bounds__(TPB, 4) void scan_kernel(
    const float* __restrict__ pos, float* __restrict__ out)
{
    // tile: pair p -> float4 {x0,x1,y0,y1} at [2p], {z0,z1,-h0,-h1} at [2p+1]
    float4* sp4 = (float4*)smem_raw;                                 // [2048]
    unsigned long long* scand =
        (unsigned long long*)(smem_raw + NNODES * 16);               // [64*CAPS]
    int* scnt = (int*)(smem_raw + NNODES * 16 + NODESB * CAPS * 8);  // [64]

    const int b     = blockIdx.x / CHUNKS;     // graph
    const int chunk = blockIdx.x % CHUNKS;
    const int tid   = threadIdx.x;
    const int n     = tid & (NODESB - 1);      // local node
    const int q     = tid >> 6;                // sub-thread id (warp-uniform)

    if (tid < NODESB) scnt[tid] = 0;

    // ---- stage packed pairs ----
    const float* gp = pos + (size_t)b * NNODES * 3;
    for (int p = tid; p < NPAIRS; p += TPB) {
        const float x0 = gp[6 * p + 0], y0 = gp[6 * p + 1], z0 = gp[6 * p + 2];
        const float x1 = gp[6 * p + 3], y1 = gp[6 * p + 4], z1 = gp[6 * p + 5];
        const float h0 = 0.5f * (x0 * x0 + y0 * y0 + z0 * z0);
        const float h1 = 0.5f * (x1 * x1 + y1 * y1 + z1 * z1);
        sp4[2 * p + 0] = make_float4(x0, x1, y0, y1);
        sp4[2 * p + 1] = make_float4(z0, z1, -h0, -h1);
    }
    __syncthreads();

    // ---- my node's data (from the packed tile) ----
    const int i = chunk * NODESB + n;
    const float4 Am = sp4[2 * (i >> 1)];
    const float4 Bm = sp4[2 * (i >> 1) + 1];
    const int par = i & 1;
    const float mex = par ? Am.y : Am.x;
    const float mey = par ? Am.w : Am.z;
    const float mez = par ? Bm.y : Bm.x;
    const float meh = -(par ? Bm.w : Bm.z);    // 0.5*|me|^2
    const float mew = 2.0f * meh;              // exact |me|^2
    // prefilter: acc >= thr  <=>  d2_approx <= 100.06 (superset of exact
    // d2 <= 100.00001 given ~0.01 fma-chain rounding slop at |p|^2 ~ 3e4)
    const float thr = meh - 50.03f;

    const unsigned long long mex2 = bcast_f32x2(mex);
    const unsigned long long mey2 = bcast_f32x2(mey);
    const unsigned long long mez2 = bcast_f32x2(mez);

    // ---- scan j-pairs; all lanes of a warp share the pair -> LDS bcast ----
    const ulonglong2* tp = (const ulonglong2*)sp4;
    const int p0 = q * SPANP;
    #pragma unroll 8
    for (int pp = 0; pp < SPANP; pp++) {
        const int pr = p0 + pp;
        const ulonglong2 A = tp[2 * pr];        // {x0,x1}, {y0,y1}
        const ulonglong2 Bv = tp[2 * pr + 1];   // {z0,z1}, {-h0,-h1}
        // acc_e = mex*x_e + mey*y_e + mez*z_e - h_e   for e in {0,1}
        unsigned long long acc = fma_f32x2(mez2, Bv.x, Bv.y);
        acc = fma_f32x2(mey2, A.y, acc);
        acc = fma_f32x2(mex2, A.x, acc);
        unsigned int ulo, uhi;
        asm("mov.b64 {%0, %1}, %2;" : "=r"(ulo), "=r"(uhi) : "l"(acc));
        const float alo = __uint_as_float(ulo);
        const float ahi = __uint_as_float(uhi);
        if (fmaxf(alo, ahi) >= thr) {           // rare (~0.8% of pair-iters)
            const float4 Af = sp4[2 * pr];
            const float4 Bf = sp4[2 * pr + 1];
            #pragma unroll
            for (int e = 0; e < 2; e++) {
                const float a_e = e ? ahi : alo;
                if (a_e < thr) continue;
                const int j = 2 * pr + e;
                const float px = e ? Af.y : Af.x;
                const float py = e ? Af.w : Af.z;
                const float pz = e ? Bf.y : Bf.x;
                const float ph = -(e ? Bf.w : Bf.z);
                // exact reference formulation (identical to prior rounds):
                const float pw  = 2.0f * ph;
                const float dot = mex * px + mey * py + mez * pz;
                const float d2  = (mew + pw) - 2.0f * dot;
                const float dist = sqrtf(fmaxf(d2, 0.0f));
                if (j != i && dist <= 10.0f) {
                    int idx = atomicAdd(&scnt[n], 1);
                    if (idx < CAPS)
                        // dist>=0 -> bit order == float order; low bits = j
                        // -> stable lower-index tie-break (matches top_k).
                        scand[n * CAPS + idx] =
                            ((unsigned long long)__float_as_uint(dist) << 32) |
                            (unsigned int)j;
                }
            }
        }
    }
    __syncthreads();

    // ---- per-node sort (ascending dist, then index); cnt ~ 8.6 avg ----
    if (tid < NODESB) {
        const int cnt = min(scnt[tid], CAPS);
        unsigned long long* c = scand + tid * CAPS;
        for (int a = 1; a < cnt; a++) {
            unsigned long long v = c[a];
            int x = a - 1;
            while (x >= 0 && c[x] > v) { c[x + 1] = c[x]; x--; }
            c[x + 1] = v;
        }
    }
    __syncthreads();

    // ---- output: thread (n,q) writes k in [q*4, q*4+4) ----
    const size_t M = (size_t)BGRAPHS * NNODES * KNBR;
    const size_t g = (size_t)b * NNODES + i;
    const int m    = min(min(scnt[n], CAPS), KNBR);
    const unsigned long long* c = scand + n * CAPS;
    const float frow = (float)g;
    const int   base = b * NNODES;

    float4 r4, c4, w4, v4;
    float* rp = (float*)&r4;
    float* cp = (float*)&c4;
    float* wp = (float*)&w4;
    float* vp = (float*)&v4;
    #pragma unroll
    for (int kk = 0; kk < 4; kk++) {
        const int k = q * 4 + kk;
        if (k < m) {
            const int j = (int)(c[k] & 0xffffffffu);
            const float4 Af = sp4[2 * (j >> 1)];
            const float4 Bf = sp4[2 * (j >> 1) + 1];
            const int pe = j & 1;
            const float px = pe ? Af.y : Af.x;
            const float py = pe ? Af.w : Af.z;
            const float pz = pe ? Bf.y : Bf.x;
            const float dx = mex - px;
            const float dy = mey - py;
            const float dz = mez - pz;
            rp[kk] = frow;
            cp[kk] = (float)(base + j);
            wp[kk] = sqrtf(dx * dx + dy * dy + dz * dz);  // recomputed, as ref
            vp[kk] = 1.0f;
        } else {
            rp[kk] = 0.0f; cp[kk] = 0.0f; wp[kk] = 0.0f; vp[kk] = 0.0f;
        }
    }
    ((float4*)(out + g * KNBR))[q]         = r4;
    ((float4*)(out + M + g * KNBR))[q]     = c4;
    ((float4*)(out + 2 * M + g * KNBR))[q] = w4;
    ((float4*)(out + 3 * M + g * KNBR))[q] = v4;
}

extern "C" void kernel_launch(void* const* d_in, const int* in_sizes, int n_in,
                              void* d_out, int out_size)
{
    const float* pos = (const float*)d_in[0];
    float* out = (float*)d_out;

    static bool attr_set = false;
    if (!attr_set) {
        cudaFuncSetAttribute(scan_kernel,
                             cudaFuncAttributeMaxDynamicSharedMemorySize,
                             SMEM_BYTES);
        attr_set = true;
    }

    dim3 grid(BGRAPHS * CHUNKS);   // 512 blocks, 4/SM resident, single wave
    scan_kernel<<<grid, TPB, SMEM_BYTES>>>(pos, out);
}

// round 7
// speedup vs baseline: 1.3768x; 1.3768x over previous
#include <cuda_runtime.h>

// DenseRadiusGraph: B=16 graphs, N=2048 nodes, D=3, cutoff=10, K=32.
// Output (float32, concat, M = B*N*K = 1048576):
//   [0,M) row ids, [M,2M) col ids, [2M,3M) weights, [3M,4M) valid flags.
//
// R7: R5 skeleton (packed LDG positions, 10.4KB smem, single wave) +
// 4-node register tile per thread: each LDG'd j is reused for 4 pairs.
// Warp reads 4 consecutive j's (one 128B line); 8-lane groups share addr.

#define BGRAPHS 16
#define NNODES  2048
#define KNBR    32
#define TPB     128
#define NODESB  32                    // nodes per block
#define RI      4                     // nodes per thread (register tile)
#define CAPS    40                    // candidate slots per node
#define CHUNKS  (NNODES / NODESB)     // 64 -> grid = 1024 blocks
#define NTOT    (BGRAPHS * NNODES)
#define WSPAN   (NNODES / 4)          // 512 j's per warp window
#define NSTEP   (WSPAN / 4)           // 128 steps (4 j's per warp per step)

// packed positions: x, y, z, 0.5*|p|^2   (512 KB device global scratch)
__device__ float4 g_packed[NTOT];

__global__ void pack_kernel(const float* __restrict__ pos)
{
    const int t = blockIdx.x * blockDim.x + threadIdx.x;
    if (t < NTOT) {
        const float x = pos[3 * t + 0];
        const float y = pos[3 * t + 1];
        const float z = pos[3 * t + 2];
        g_packed[t] = make_float4(x, y, z, 0.5f * (x * x + y * y + z * z));
    }
}

__global__ __launch_bounds__(TPB, 7) void scan_kernel(float* __restrict__ out)
{
    __shared__ unsigned long long scand[NODESB * CAPS];
    __shared__ int scnt[NODESB];

    const int b     = blockIdx.x / CHUNKS;     // graph
    const int chunk = blockIdx.x % CHUNKS;
    const int tid   = threadIdx.x;
    const int lane  = tid & 31;
    const int w     = tid >> 5;                // warp id (0..3)
    const int g     = lane & 7;                // node sub-group (0..7)
    const int ql    = lane >> 3;               // j-offset within quad (0..3)

    if (tid < NODESB) scnt[tid] = 0;
    __syncthreads();

    const float4* __restrict__ gp = g_packed + b * NNODES;
    const int i0 = chunk * NODESB;

    // ---- my 4 nodes in registers ----
    float mx[RI], my[RI], mz[RI], mh[RI];      // xyz and 0.5|p|^2 (exact)
    #pragma unroll
    for (int r = 0; r < RI; r++) {
        const float4 me = __ldg(&gp[i0 + g + 8 * r]);
        mx[r] = me.x; my[r] = me.y; mz[r] = me.z; mh[r] = me.w;
    }

    // ---- scan: warp w covers j in [w*512, w*512+512), 4 consecutive j
    //      per step (one 128B line per warp-LDG); 8 lanes share each addr ----
    const int jbase = w * WSPAN + ql;
    #pragma unroll 4
    for (int s = 0; s < NSTEP; s++) {
        const int j = jbase + 4 * s;
        const float4 p = __ldg(&gp[j]);
        // filter: dot(me_r,p) - h_i_r  >=  h_j - 50.03
        // (superset of exact d2 <= 100.00001; ~0.01 fma-chain slop vs
        //  the 0.06 d2-margin; exact test re-applied below)
        const float rhs = p.w - 50.03f;
        float a[RI];
        #pragma unroll
        for (int r = 0; r < RI; r++)
            a[r] = fmaf(mx[r], p.x, fmaf(my[r], p.y, fmaf(mz[r], p.z, -mh[r])));
        const float amax = fmaxf(fmaxf(a[0], a[1]), fmaxf(a[2], a[3]));
        if (amax >= rhs) {                     // rare (~1.7% of steps)
            const float pw = 2.0f * p.w;       // exact |p_j|^2
            #pragma unroll
            for (int r = 0; r < RI; r++) {
                if (a[r] >= rhs) {
                    const int n_r  = g + 8 * r;
                    const int irow = i0 + n_r;
                    // exact reference formulation (bit-identical to R5):
                    const float mew = 2.0f * mh[r];
                    const float dot = mx[r] * p.x + my[r] * p.y + mz[r] * p.z;
                    const float d2  = (mew + pw) - 2.0f * dot;
                    const float dist = sqrtf(fmaxf(d2, 0.0f));
                    if (j != irow && dist <= 10.0f) {
                        int idx = atomicAdd(&scnt[n_r], 1);
                        if (idx < CAPS)
                            // dist>=0 -> bit order == float order; low bits
                            // = j -> stable lower-index tie-break (top_k).
                            scand[n_r * CAPS + idx] =
                                ((unsigned long long)__float_as_uint(dist) << 32) |
                                (unsigned int)j;
                    }
                }
            }
        }
    }
    __syncthreads();

    // ---- per-node sort (ascending dist, then index); cnt ~ 8.6 avg ----
    if (tid < NODESB) {
        const int cnt = min(scnt[tid], CAPS);
        unsigned long long* c = scand + tid * CAPS;
        for (int a2 = 1; a2 < cnt; a2++) {
            unsigned long long v = c[a2];
            int x = a2 - 1;
            while (x >= 0 && c[x] > v) { c[x + 1] = c[x]; x--; }
            c[x + 1] = v;
        }
    }
    __syncthreads();

    // ---- output: thread t -> node (t&31), k-slice (t>>5)*8 .. +8 ----
    const int n  = tid & (NODESB - 1);
    const int q8 = tid >> 5;                   // 0..3, 8 k's each
    const size_t M = (size_t)BGRAPHS * NNODES * KNBR;
    const int i = i0 + n;
    const size_t gidx = (size_t)b * NNODES + i;
    const int m = min(min(scnt[n], CAPS), KNBR);
    const unsigned long long* c = scand + n * CAPS;
    const float frow = (float)gidx;
    const int   base = b * NNODES;
    const float4 meo = __ldg(&gp[i]);

    float* __restrict__ orow = out + gidx * KNBR + q8 * 8;
    float* __restrict__ ocol = out + M + gidx * KNBR + q8 * 8;
    float* __restrict__ ow   = out + 2 * M + gidx * KNBR + q8 * 8;
    float* __restrict__ oval = out + 3 * M + gidx * KNBR + q8 * 8;

    #pragma unroll
    for (int k4 = 0; k4 < 2; k4++) {
        float4 r4, c4, w4, v4;
        float* rp = (float*)&r4;
        float* cp = (float*)&c4;
        float* wp = (float*)&w4;
        float* vp = (float*)&v4;
        #pragma unroll
        for (int kk = 0; kk < 4; kk++) {
            const int k = q8 * 8 + k4 * 4 + kk;
            if (k < m) {
                const int j = (int)(c[k] & 0xffffffffu);
                const float4 p = __ldg(&gp[j]);
                const float dx = meo.x - p.x;
                const float dy = meo.y - p.y;
                const float dz = meo.z - p.z;
                rp[kk] = frow;
                cp[kk] = (float)(base + j);
                wp[kk] = sqrtf(dx * dx + dy * dy + dz * dz);  // as reference
                vp[kk] = 1.0f;
            } else {
                rp[kk] = 0.0f; cp[kk] = 0.0f; wp[kk] = 0.0f; vp[kk] = 0.0f;
            }
        }
        ((float4*)orow)[k4] = r4;
        ((float4*)ocol)[k4] = c4;
        ((float4*)ow  )[k4] = w4;
        ((float4*)oval)[k4] = v4;
    }
}

extern "C" void kernel_launch(void* const* d_in, const int* in_sizes, int n_in,
                              void* d_out, int out_size)
{
    const float* pos = (const float*)d_in[0];
    float* out = (float*)d_out;

    pack_kernel<<<(NTOT + 255) / 256, 256>>>(pos);
    scan_kernel<<<BGRAPHS * CHUNKS, TPB>>>(out);   // 1024 blocks, one wave
}

// round 8
// speedup vs baseline: 2.2055x; 1.6019x over previous
#include <cuda_runtime.h>

// DenseRadiusGraph: B=16 graphs, N=2048 nodes, D=3, cutoff=10, K=32.
// Output (float32, concat, M = B*N*K = 1048576):
//   [0,M) row ids, [M,2M) col ids, [2M,3M) weights, [3M,4M) valid flags.
//
// R8: spatial binning. Cells of width 10 (=cutoff) -> each node scans only
// its 27-cell neighborhood (~55 candidates vs 2048): ~37x less pair work.
// Exact per-candidate test identical (bit-for-bit) to the O(N^2) rounds.

#define BGRAPHS 16
#define NNODES  2048
#define KNBR    32
#define NTOT    (BGRAPHS * NNODES)
#define NCELL   1000                  // 10x10x10
#define NODESB  32
#define CHUNKS  (NNODES / NODESB)     // 64 -> scan grid = 1024 blocks
#define CAPS    40
#define TPB_A   256
#define TPB_B   288                   // 9 warps: one (dx,dy) column each

typedef unsigned long long ull;

// device scratch (static globals -- no allocation)
__device__ float4 g_packed[NTOT];              // x,y,z, 0.5*|p|^2
__device__ float4 g_sorted[NTOT];              // cell-sorted copy of g_packed
__device__ int    g_sidx[NTOT];                // original index of sorted entry
__device__ int    g_cellstart[BGRAPHS][NCELL + 1];

__device__ __forceinline__ int3 cell_of(float x, float y, float z)
{
    return make_int3(min(9, (int)(x * 0.1f)),
                     min(9, (int)(y * 0.1f)),
                     min(9, (int)(z * 0.1f)));
}

__global__ void pack_kernel(const float* __restrict__ pos)
{
    const int t = blockIdx.x * blockDim.x + threadIdx.x;
    if (t < NTOT) {
        const float x = pos[3 * t + 0];
        const float y = pos[3 * t + 1];
        const float z = pos[3 * t + 2];
        g_packed[t] = make_float4(x, y, z, 0.5f * (x * x + y * y + z * z));
    }
}

// one block per graph: histogram -> prefix sum -> scatter
__global__ __launch_bounds__(TPB_A) void bin_kernel()
{
    __shared__ int cellid[NNODES];
    __shared__ int cnt[NCELL];          // counts, then scatter cursors
    __shared__ int start[NCELL + 1];
    __shared__ int psum[250];

    const int b = blockIdx.x;
    const int t = threadIdx.x;

    for (int c = t; c < NCELL; c += TPB_A) cnt[c] = 0;
    __syncthreads();

    const float4* gp = g_packed + (size_t)b * NNODES;
    for (int n = t; n < NNODES; n += TPB_A) {
        const float4 p = gp[n];
        const int3 cc = cell_of(p.x, p.y, p.z);
        const int c = (cc.x * 10 + cc.y) * 10 + cc.z;
        cellid[n] = c;
        atomicAdd(&cnt[c], 1);
    }
    __syncthreads();

    // exclusive prefix sum over 1000 cells: 250 threads x 4, serial middle
    if (t < 250) {
        int s = 0;
        #pragma unroll
        for (int k = 0; k < 4; k++) s += cnt[4 * t + k];
        psum[t] = s;
    }
    __syncthreads();
    if (t == 0) {
        int acc = 0;
        for (int k = 0; k < 250; k++) { int v = psum[k]; psum[k] = acc; acc += v; }
    }
    __syncthreads();
    if (t < 250) {
        int acc = psum[t];
        #pragma unroll
        for (int k = 0; k < 4; k++) {
            const int v = cnt[4 * t + k];
            start[4 * t + k] = acc;
            cnt[4 * t + k]   = acc;     // cursor
            acc += v;
        }
    }
    if (t == 0) start[NCELL] = NNODES;
    __syncthreads();

    for (int n = t; n < NNODES; n += TPB_A) {
        const int p = atomicAdd(&cnt[cellid[n]], 1);
        g_sorted[(size_t)b * NNODES + p] = gp[n];   // bitwise copy (h intact)
        g_sidx[(size_t)b * NNODES + p]  = n;
    }
    for (int c = t; c <= NCELL; c += TPB_A) g_cellstart[b][c] = start[c];
}

__global__ __launch_bounds__(TPB_B, 7) void scan_kernel(float* __restrict__ out)
{
    __shared__ ull scand[NODESB * CAPS];
    __shared__ int scnt[NODESB];

    const int b     = blockIdx.x / CHUNKS;
    const int chunk = blockIdx.x % CHUNKS;
    const int t     = threadIdx.x;
    const int lane  = t & 31;
    const int s     = t >> 5;                 // 0..8: (dx,dy) column

    if (t < NODESB) scnt[t] = 0;
    __syncthreads();

    const float4* __restrict__ gp = g_packed + (size_t)b * NNODES;
    const int i = chunk * NODESB + lane;      // original node index
    const float4 me = gp[i];
    const float mew = 2.0f * me.w;            // exact |me|^2

    const int3 cc = cell_of(me.x, me.y, me.z);
    const int cxn = cc.x + (s / 3) - 1;
    const int cyn = cc.y + (s % 3) - 1;

    if (cxn >= 0 && cxn < 10 && cyn >= 0 && cyn < 10) {
        const int basec = (cxn * 10 + cyn) * 10;
        const int zlo = max(cc.z - 1, 0);
        const int zhi = min(cc.z + 1, 9);
        const int lo = g_cellstart[b][basec + zlo];
        const int hi = g_cellstart[b][basec + zhi + 1];

        const float4* __restrict__ gs = g_sorted + (size_t)b * NNODES;
        const int*    __restrict__ gi = g_sidx + (size_t)b * NNODES;

        for (int idx = lo; idx < hi; idx++) {
            const float4 pj = gs[idx];
            // exact reference formulation, bit-identical to prior rounds:
            const float pw  = 2.0f * pj.w;
            const float dot = me.x * pj.x + me.y * pj.y + me.z * pj.z;
            const float d2  = (mew + pw) - 2.0f * dot;
            const float dist = sqrtf(fmaxf(d2, 0.0f));
            const int j = gi[idx];
            if (j != i && dist <= 10.0f) {
                int c = atomicAdd(&scnt[lane], 1);
                if (c < CAPS)
                    // dist>=0 -> bit order == float order; low bits = j ->
                    // stable lower-index tie-break (matches lax.top_k).
                    scand[lane * CAPS + c] =
                        ((ull)__float_as_uint(dist) << 32) | (unsigned int)j;
            }
        }
    }
    __syncthreads();

    // per-node sort (ascending dist, then index); cnt ~ 8.6 avg
    if (t < NODESB) {
        const int cnt = min(scnt[t], CAPS);
        ull* c = scand + t * CAPS;
        for (int a = 1; a < cnt; a++) {
            ull v = c[a];
            int x = a - 1;
            while (x >= 0 && c[x] > v) { c[x + 1] = c[x]; x--; }
            c[x + 1] = v;
        }
    }
    __syncthreads();

    // output: threads 0..255 -> node (t&31), k-slice (t>>5)*4 .. +4
    if (t < 256) {
        const int n  = t & 31;
        const int q  = t >> 5;                // 0..7
        const size_t M = (size_t)BGRAPHS * NNODES * KNBR;
        const int in = chunk * NODESB + n;
        const size_t gidx = (size_t)b * NNODES + in;
        const int m = min(min(scnt[n], CAPS), KNBR);
        const ull* c = scand + n * CAPS;
        const float frow = (float)gidx;
        const int   base = b * NNODES;
        const float4 meo = gp[in];

        float4 r4, c4, w4, v4;
        float* rp = (float*)&r4;
        float* cp = (float*)&c4;
        float* wp = (float*)&w4;
        float* vp = (float*)&v4;
        #pragma unroll
        for (int kk = 0; kk < 4; kk++) {
            const int k = q * 4 + kk;
            if (k < m) {
                const int j = (int)(c[k] & 0xffffffffu);
                const float4 p = gp[j];
                const float dx = meo.x - p.x;
                const float dy = meo.y - p.y;
                const float dz = meo.z - p.z;
                rp[kk] = frow;
                cp[kk] = (float)(base + j);
                wp[kk] = sqrtf(dx * dx + dy * dy + dz * dz);  // as reference
                vp[kk] = 1.0f;
            } else {
                rp[kk] = 0.0f; cp[kk] = 0.0f; wp[kk] = 0.0f; vp[kk] = 0.0f;
            }
        }
        ((float4*)(out + gidx * KNBR))[q]         = r4;
        ((float4*)(out + M + gidx * KNBR))[q]     = c4;
        ((float4*)(out + 2 * M + gidx * KNBR))[q] = w4;
        ((float4*)(out + 3 * M + gidx * KNBR))[q] = v4;
    }
}

extern "C" void kernel_launch(void* const* d_in, const int* in_sizes, int n_in,
                              void* d_out, int out_size)
{
    const float* pos = (const float*)d_in[0];
    float* out = (float*)d_out;

    pack_kernel<<<(NTOT + 255) / 256, 256>>>(pos);
    bin_kernel<<<BGRAPHS, TPB_A>>>();
    scan_kernel<<<BGRAPHS * CHUNKS, TPB_B>>>(out);
}

// round 11
// speedup vs baseline: 2.6232x; 1.1894x over previous
#include <cuda_runtime.h>

// DenseRadiusGraph: B=16 graphs, N=2048 nodes, D=3, cutoff=10, K=32.
// Output (float32, concat, M = B*N*K = 1048576):
//   [0,M) row ids, [M,2M) col ids, [2M,3M) weights, [3M,4M) valid flags.
//
// R10: R9 (fused pack+bin, parallel prefix, sorted-order scan for coherent
// gathers) with the prefix-sum OOB fixed: cell count/start arrays padded to
// 1024 so the 256x4 scan never indexes past the end (R9 wrote cnt[1000..1023]
// out of bounds -> corrupted cursors -> global OOB scatter -> crash).

#define BGRAPHS 16
#define NNODES  2048
#define KNBR    32
#define NTOT    (BGRAPHS * NNODES)
#define NCELL   1000                  // 10x10x10 cells of width 10 = cutoff
#define NCELLP  1024                  // padded to 256*4 for the prefix scan
#define NODESB  32
#define CHUNKS  (NNODES / NODESB)     // 64 -> scan grid = 1024 blocks
#define CAPS    40
#define TPB_A   1024
#define TPB_B   288                   // 9 warps: one (dx,dy) column each

typedef unsigned long long ull;

// device scratch (static globals -- no allocation)
__device__ float4 g_packed[NTOT];              // x,y,z, 0.5*|p|^2  (orig order)
__device__ float4 g_sorted[NTOT];              // cell-sorted copy
__device__ int    g_sidx[NTOT];                // original index of sorted entry
__device__ int    g_cellstart[BGRAPHS][NCELL + 1];

__device__ __forceinline__ int3 cell_of(float x, float y, float z)
{
    return make_int3(min(9, (int)(x * 0.1f)),
                     min(9, (int)(y * 0.1f)),
                     min(9, (int)(z * 0.1f)));
}

// one block per graph: pack + histogram -> parallel prefix -> scatter
__global__ __launch_bounds__(TPB_A) void bin_kernel(const float* __restrict__ pos)
{
    __shared__ int cellid[NNODES];
    __shared__ int cnt[NCELLP];         // counts, then scatter cursors (padded)
    __shared__ int start[NCELLP + 1];
    __shared__ int partial[256];        // 4-cell partials for prefix scan

    const int b = blockIdx.x;
    const int t = threadIdx.x;

    for (int c = t; c < NCELLP; c += TPB_A) cnt[c] = 0;   // pad cells stay 0
    __syncthreads();

    const float* gpos = pos + (size_t)b * NNODES * 3;
    for (int n = t; n < NNODES; n += TPB_A) {
        const float x = gpos[3 * n + 0];
        const float y = gpos[3 * n + 1];
        const float z = gpos[3 * n + 2];
        g_packed[(size_t)b * NNODES + n] =
            make_float4(x, y, z, 0.5f * (x * x + y * y + z * z));
        const int3 cc = cell_of(x, y, z);
        const int c = (cc.x * 10 + cc.y) * 10 + cc.z;
        cellid[n] = c;
        atomicAdd(&cnt[c], 1);
    }
    __syncthreads();

    // inclusive Hillis-Steele over 256 partials (each = 4 cells, 1024 total)
    int own = 0;
    if (t < 256) {
        #pragma unroll
        for (int k = 0; k < 4; k++) own += cnt[4 * t + k];
        partial[t] = own;
    }
    __syncthreads();
    #pragma unroll
    for (int off = 1; off < 256; off <<= 1) {
        int v = 0;
        if (t < 256 && t >= off) v = partial[t - off];
        __syncthreads();
        if (t < 256) partial[t] += v;
        __syncthreads();
    }
    if (t < 256) {
        int acc = partial[t] - own;     // exclusive base for my 4 cells
        #pragma unroll
        for (int k = 0; k < 4; k++) {
            const int v = cnt[4 * t + k];
            start[4 * t + k] = acc;     // in-bounds: 4t+k < 1024 = NCELLP
            cnt[4 * t + k]   = acc;     // scatter cursor
            acc += v;
        }
    }
    // pad cells are empty -> start[NCELL] == NNODES automatically
    __syncthreads();

    for (int n = t; n < NNODES; n += TPB_A) {
        const int p = atomicAdd(&cnt[cellid[n]], 1);
        g_sorted[(size_t)b * NNODES + p] = g_packed[(size_t)b * NNODES + n];
        g_sidx[(size_t)b * NNODES + p]  = n;
    }
    for (int c = t; c <= NCELL; c += TPB_A) g_cellstart[b][c] = start[c];
}

__global__ __launch_bounds__(TPB_B, 7) void scan_kernel(float* __restrict__ out)
{
    __shared__ ull scand[NODESB * CAPS];
    __shared__ int scnt[NODESB];

    const int b     = blockIdx.x / CHUNKS;
    const int chunk = blockIdx.x % CHUNKS;
    const int t     = threadIdx.x;
    const int lane  = t & 31;
    const int s     = t >> 5;                 // 0..8: (dx,dy) column

    if (t < NODESB) scnt[t] = 0;
    __syncthreads();

    const float4* __restrict__ gs = g_sorted + (size_t)b * NNODES;
    const int*    __restrict__ gi = g_sidx   + (size_t)b * NNODES;

    const int sp = chunk * NODESB + lane;     // SORTED position (coherent)
    const float4 me = gs[sp];
    const int i = gi[sp];                     // original node index
    const float mew = 2.0f * me.w;            // exact |me|^2

    const int3 cc = cell_of(me.x, me.y, me.z);
    const int cxn = cc.x + (s / 3) - 1;
    const int cyn = cc.y + (s % 3) - 1;

    if (cxn >= 0 && cxn < 10 && cyn >= 0 && cyn < 10) {
        const int basec = (cxn * 10 + cyn) * 10;
        const int zlo = max(cc.z - 1, 0);
        const int zhi = min(cc.z + 1, 9);
        const int lo = g_cellstart[b][basec + zlo];
        const int hi = g_cellstart[b][basec + zhi + 1];

        for (int idx = lo; idx < hi; idx++) {
            const float4 pj = gs[idx];        // lanes' ranges overlap -> few lines
            // exact reference formulation, bit-identical to prior rounds:
            const float pw  = 2.0f * pj.w;
            const float dot = me.x * pj.x + me.y * pj.y + me.z * pj.z;
            const float d2  = (mew + pw) - 2.0f * dot;
            const float dist = sqrtf(fmaxf(d2, 0.0f));
            const int j = gi[idx];
            if (j != i && dist <= 10.0f) {
                int c = atomicAdd(&scnt[lane], 1);
                if (c < CAPS)
                    // dist>=0 -> bit order == float order; low bits = j ->
                    // stable lower-index tie-break (matches lax.top_k).
                    scand[lane * CAPS + c] =
                        ((ull)__float_as_uint(dist) << 32) | (unsigned int)j;
            }
        }
    }
    __syncthreads();

    // per-node sort (ascending dist, then index); cnt ~ 8.6 avg
    if (t < NODESB) {
        const int cnt = min(scnt[t], CAPS);
        ull* c = scand + t * CAPS;
        for (int a = 1; a < cnt; a++) {
            ull v = c[a];
            int x = a - 1;
            while (x >= 0 && c[x] > v) { c[x + 1] = c[x]; x--; }
            c[x + 1] = v;
        }
    }
    __syncthreads();

    // output: threads 0..255 -> node slot (t&31), k-slice (t>>5)*4 .. +4
    if (t < 256) {
        const int n  = t & 31;
        const int q  = t >> 5;                // 0..7
        const size_t M = (size_t)BGRAPHS * NNODES * KNBR;
        const int in = gi[chunk * NODESB + n];        // original node id
        const float4 meo = gs[chunk * NODESB + n];
        const size_t gidx = (size_t)b * NNODES + in;
        const int m = min(min(scnt[n], CAPS), KNBR);
        const ull* c = scand + n * CAPS;
        const float frow = (float)gidx;
        const int   base = b * NNODES;
        const float4* __restrict__ gp = g_packed + (size_t)b * NNODES;

        float4 r4, c4, w4, v4;
        float* rp = (float*)&r4;
        float* cp = (float*)&c4;
        float* wp = (float*)&w4;
        float* vp = (float*)&v4;
        #pragma unroll
        for (int kk = 0; kk < 4; kk++) {
            const int k = q * 4 + kk;
            if (k < m) {
                const int j = (int)(c[k] & 0xffffffffu);
                const float4 p = gp[j];
                const float dx = meo.x - p.x;
                const float dy = meo.y - p.y;
                const float dz = meo.z - p.z;
                rp[kk] = frow;
                cp[kk] = (float)(base + j);
                wp[kk] = sqrtf(dx * dx + dy * dy + dz * dz);  // as reference
                vp[kk] = 1.0f;
            } else {
                rp[kk] = 0.0f; cp[kk] = 0.0f; wp[kk] = 0.0f; vp[kk] = 0.0f;
            }
        }
        ((float4*)(out + gidx * KNBR))[q]         = r4;
        ((float4*)(out + M + gidx * KNBR))[q]     = c4;
        ((float4*)(out + 2 * M + gidx * KNBR))[q] = w4;
        ((float4*)(out + 3 * M + gidx * KNBR))[q] = v4;
    }
}

extern "C" void kernel_launch(void* const* d_in, const int* in_sizes, int n_in,
                              void* d_out, int out_size)
{
    const float* pos = (const float*)d_in[0];
    float* out = (float*)d_out;

    bin_kernel<<<BGRAPHS, TPB_A>>>(pos);
    scan_kernel<<<BGRAPHS * CHUNKS, TPB_B>>>(out);
}